// round 5
// baseline (speedup 1.0000x reference)
#include <cuda_runtime.h>
#include <math.h>

// Problem constants
#define BB 512
#define TT 512
#define II 8
#define HH 256

// Partitioning: 8 batch tiles x 16 h-column tiles = 128 CTAs (single wave on 148 SMs)
#define NBT 8
#define NCT 16
#define BT 64          // batch rows per CTA
#define CT 16          // h columns per CTA (=> 48 gh columns: r,z,n)
#define NCTAS (NBT * NCT)
#define NTHREADS 256

// SMEM pitches (in float4) chosen so W reads are bank-conflict-free:
// row stride = 65 float4 = 260 words; 260 mod 32 = 4 => 16 consecutive rows
// start at bank-quads {0,4,...,28} -> exactly 2 addresses per bank = 2-phase min.
#define WS_PITCH 65
#define HS_PITCH 65

// Persistent device state (no allocation allowed in kernel_launch)
__device__ float g_h[2][BB][HH];          // ping-pong hidden state
__device__ unsigned g_bar_count = 0;
__device__ unsigned g_bar_gen = 0;

__device__ __forceinline__ void grid_barrier() {
    __syncthreads();
    if (threadIdx.x == 0) {
        __threadfence();                                  // publish h stores / out stores
        volatile unsigned* vgen = (volatile unsigned*)&g_bar_gen;
        unsigned gen = *vgen;
        unsigned arrived = atomicAdd(&g_bar_count, 1u);
        if (arrived == NCTAS - 1u) {
            *((volatile unsigned*)&g_bar_count) = 0u;     // reset before release
            __threadfence();
            *vgen = gen + 1u;                             // release
        } else {
            while (*vgen == gen) { }                      // L2 spin (~250cyc/poll)
        }
        __threadfence();
    }
    __syncthreads();
}

__device__ __forceinline__ float sigmoidf_fast(float v) {
    return 1.0f / (1.0f + __expf(-v));
}

__global__ void __launch_bounds__(NTHREADS, 1)
gru_persistent_kernel(const float* __restrict__ x,
                      const float* __restrict__ W_ih,
                      const float* __restrict__ W_hh,
                      const float* __restrict__ b_ih,
                      const float* __restrict__ b_hh,
                      const float* __restrict__ W_lin,
                      const float* __restrict__ b_lin,
                      float* __restrict__ out)
{
    extern __shared__ char smem_raw[];
    float4* ws4 = (float4*)smem_raw;                 // [48][WS_PITCH] W_hh slice (k-major)
    float4* hs4 = ws4 + 48 * WS_PITCH;               // [64][HS_PITCH] h tile (k-major)
    float*  wih  = (float*)(hs4 + 64 * HS_PITCH);    // [48][9]  W_ih slice (padded)
    float*  xs   = wih + 48 * 9;                     // [64][8]  x_t tile
    float*  bihs = xs + 64 * 8;                      // [48]
    float*  bhhs = bihs + 48;                        // [48]
    float*  wlin = bhhs + 48;                        // [16]

    const int tid = threadIdx.x;
    const int cta = blockIdx.x;
    const int bt  = cta / NCT;
    const int ct  = cta % NCT;
    const int b0  = bt * BT;
    const int j0  = ct * CT;

    // ---- one-time: load weight slices into SMEM (resident for all 512 steps) ----
    {
        const float4* whh4 = (const float4*)W_hh;    // rows of 256 floats = 64 float4
        for (int idx = tid; idx < 48 * 64; idx += NTHREADS) {
            int c = idx >> 6, k4 = idx & 63;
            int g = c >> 4, l = c & 15;
            int grow = g * HH + j0 + l;              // W_hh row index (gate-major)
            ws4[c * WS_PITCH + k4] = whh4[grow * (HH / 4) + k4];
        }
        for (int idx = tid; idx < 48 * II; idx += NTHREADS) {
            int c = idx >> 3, k = idx & 7;
            int g = c >> 4, l = c & 15;
            int grow = g * HH + j0 + l;
            wih[c * 9 + k] = W_ih[grow * II + k];
        }
        if (tid < 48) {
            int g = tid >> 4, l = tid & 15;
            int grow = g * HH + j0 + l;
            bihs[tid] = b_ih[grow];
            bhhs[tid] = b_hh[grow];
        }
        if (tid < CT) wlin[tid] = W_lin[j0 + tid];
    }

    // ---- one-time: h0 = 0, out = b_lin (out is accumulated via atomics) ----
    {
        float* h0 = &g_h[0][0][0];
        const int perH = (BB * HH) / NCTAS;          // 1024
        for (int i = tid; i < perH; i += NTHREADS) h0[cta * perH + i] = 0.0f;
        const float bl = b_lin[0];
        const int perO = (BB * TT) / NCTAS;          // 2048
        for (int i = tid; i < perO; i += NTHREADS) out[(size_t)cta * perO + i] = bl;
    }

    grid_barrier();

    const int ty = tid >> 4;                         // 0..15 -> 4 batch rows each
    const int tx = tid & 15;                         // 0..15 -> 1 h-col each (x3 gates)

    for (int t = 0; t < TT; t++) {
        const int p = t & 1;

        // load h tile [64][256] from L2 (ping buffer), bypassing L1 for coherence
        const float4* hsrc = (const float4*)&g_h[p][b0][0];
        for (int idx = tid; idx < 64 * 64; idx += NTHREADS) {
            int r = idx >> 6, k4 = idx & 63;
            hs4[r * HS_PITCH + k4] = __ldcg(&hsrc[r * 64 + k4]);
        }
        // load x_t tile [64][8]
        if (tid < BT * 2) {
            int r = tid >> 1, half = tid & 1;
            const float4* xsrc = (const float4*)&x[((size_t)(b0 + r) * TT + t) * II];
            ((float4*)xs)[r * 2 + half] = __ldg(&xsrc[half]);
        }
        __syncthreads();

        // ---- GEMM: acc[g][i] = sum_k h[4ty+i][k] * W_hh[g*256 + j0+tx][k] ----
        float acc0[4], acc1[4], acc2[4];
        #pragma unroll
        for (int i = 0; i < 4; i++) { acc0[i] = 0.f; acc1[i] = 0.f; acc2[i] = 0.f; }

        const float4* hp  = hs4 + (4 * ty) * HS_PITCH;
        const float4* w0p = ws4 + tx * WS_PITCH;
        const float4* w1p = ws4 + (16 + tx) * WS_PITCH;
        const float4* w2p = ws4 + (32 + tx) * WS_PITCH;

        #pragma unroll 4
        for (int k4 = 0; k4 < 64; k4++) {
            float4 w0 = w0p[k4];
            float4 w1 = w1p[k4];
            float4 w2 = w2p[k4];
            #pragma unroll
            for (int i = 0; i < 4; i++) {
                float4 hv = hp[i * HS_PITCH + k4];
                acc0[i] += hv.x * w0.x + hv.y * w0.y + hv.z * w0.z + hv.w * w0.w;
                acc1[i] += hv.x * w1.x + hv.y * w1.y + hv.z * w1.z + hv.w * w1.w;
                acc2[i] += hv.x * w2.x + hv.y * w2.y + hv.z * w2.z + hv.w * w2.w;
            }
        }

        // ---- fused gates + h update + pred partial ----
        float pred[4];
        #pragma unroll
        for (int i = 0; i < 4; i++) {
            const int r = 4 * ty + i;
            float gr = bihs[tx], gz = bihs[16 + tx], gn = bihs[32 + tx];
            #pragma unroll
            for (int k = 0; k < II; k++) {
                float xv = xs[r * II + k];
                gr += xv * wih[tx * 9 + k];
                gz += xv * wih[(16 + tx) * 9 + k];
                gn += xv * wih[(32 + tx) * 9 + k];
            }
            float rr = sigmoidf_fast(gr + acc0[i] + bhhs[tx]);
            float zz = sigmoidf_fast(gz + acc1[i] + bhhs[16 + tx]);
            float nn = tanhf(gn + rr * (acc2[i] + bhhs[32 + tx]));
            float hold = ((const float*)hs4)[r * (HS_PITCH * 4) + j0 + tx];
            float hn = (1.0f - zz) * nn + zz * hold;
            __stcg(&g_h[1 - p][b0 + r][j0 + tx], hn);
            pred[i] = hn * wlin[tx];
        }

        // reduce pred over the 16 tx lanes (low 4 lane bits), then atomic into out
        #pragma unroll
        for (int i = 0; i < 4; i++) {
            float v = pred[i];
            v += __shfl_xor_sync(0xffffffffu, v, 1);
            v += __shfl_xor_sync(0xffffffffu, v, 2);
            v += __shfl_xor_sync(0xffffffffu, v, 4);
            v += __shfl_xor_sync(0xffffffffu, v, 8);
            if (tx == 0) atomicAdd(&out[(size_t)(b0 + 4 * ty + i) * TT + t], v);
        }

        grid_barrier();   // h[1-p] fully written chip-wide before next step reads it
    }
}

extern "C" void kernel_launch(void* const* d_in, const int* in_sizes, int n_in,
                              void* d_out, int out_size) {
    const float* x     = (const float*)d_in[0];
    const float* W_ih  = (const float*)d_in[1];
    const float* W_hh  = (const float*)d_in[2];
    const float* b_ih  = (const float*)d_in[3];
    const float* b_hh  = (const float*)d_in[4];
    const float* W_lin = (const float*)d_in[5];
    const float* b_lin = (const float*)d_in[6];
    float* out = (float*)d_out;

    size_t smem = (size_t)(48 * WS_PITCH + 64 * HS_PITCH) * sizeof(float4)
                + (size_t)(48 * 9 + 64 * 8 + 48 + 48 + 16) * sizeof(float);

    cudaFuncSetAttribute(gru_persistent_kernel,
                         cudaFuncAttributeMaxDynamicSharedMemorySize, (int)smem);

    gru_persistent_kernel<<<NCTAS, NTHREADS, smem>>>(
        x, W_ih, W_hh, b_ih, b_hh, W_lin, b_lin, out);
}

// round 7
// speedup vs baseline: 1.0854x; 1.0854x over previous
#include <cuda_runtime.h>
#include <math.h>

// Problem constants
#define BB 512
#define TT 512
#define II 8
#define HH 256

// Partitioning: 8 batch tiles x 16 h-column tiles = 128 CTAs (single wave)
#define NBT 8
#define NCT 16
#define BT 64          // batch rows per CTA
#define CT 16          // h columns per CTA (=> 48 gh columns: r,z,n)
#define NCTAS (NBT * NCT)
#define NTHREADS 256

// SMEM pitches in float4 (row stride 65*16B keeps W reads at 2-phase min,
// h reads broadcast)
#define WS_PITCH 65
#define HS_PITCH 65
#define WIH_PITCH 10   // floats; even => 8B-aligned u64 pairs

// Persistent device state
__device__ float g_h[2][BB][HH];
__device__ unsigned g_bar_count = 0;
__device__ unsigned g_bar_gen = 0;

__device__ __forceinline__ void grid_barrier() {
    __syncthreads();
    if (threadIdx.x == 0) {
        __threadfence();
        volatile unsigned* vgen = (volatile unsigned*)&g_bar_gen;
        unsigned gen = *vgen;
        unsigned arrived = atomicAdd(&g_bar_count, 1u);
        if (arrived == NCTAS - 1u) {
            *((volatile unsigned*)&g_bar_count) = 0u;
            __threadfence();
            *vgen = gen + 1u;
        } else {
            while (*vgen == gen) { }
        }
        __threadfence();
    }
    __syncthreads();
}

__device__ __forceinline__ float sigmoidf_fast(float v) {
    return 1.0f / (1.0f + __expf(-v));
}

// tanh via exp (MUFU path). Clamp avoids inf/inf NaN for |v|>44.
__device__ __forceinline__ float tanh_fast(float v) {
    v = fminf(fmaxf(v, -15.0f), 15.0f);
    float e = __expf(-2.0f * v);
    return __fdividef(1.0f - e, 1.0f + e);
}

// Blackwell packed dual-fp32 FMA: d(lo,hi) += a(lo,hi)*b(lo,hi)
__device__ __forceinline__ void ffma2(unsigned long long& d,
                                      unsigned long long a,
                                      unsigned long long b) {
    asm("fma.rn.f32x2 %0, %1, %2, %0;" : "+l"(d) : "l"(a), "l"(b));
}

__device__ __forceinline__ float f2sum(unsigned long long v) {
    return __uint_as_float((unsigned)v) + __uint_as_float((unsigned)(v >> 32));
}

// One 16-k4 GEMM chunk: wait for its cp.async group, sync, then FFMA2 over it.
#define CHUNK(CBASE, WAITN)                                                   \
  {                                                                           \
    asm volatile("cp.async.wait_group " #WAITN ";" ::: "memory");             \
    __syncthreads();                                                          \
    _Pragma("unroll 4")                                                       \
    for (int kk = 0; kk < 16; kk++) {                                         \
      const int k4 = (CBASE) + kk;                                            \
      ulonglong2 w0 = w0q[k4], w1 = w1q[k4], w2 = w2q[k4];                    \
      _Pragma("unroll")                                                       \
      for (int i = 0; i < 4; i++) {                                           \
        ulonglong2 hv = hq[i][k4];                                            \
        ffma2(acc0[i], hv.x, w0.x); ffma2(acc0[i], hv.y, w0.y);               \
        ffma2(acc1[i], hv.x, w1.x); ffma2(acc1[i], hv.y, w1.y);               \
        ffma2(acc2[i], hv.x, w2.x); ffma2(acc2[i], hv.y, w2.y);               \
      }                                                                       \
    }                                                                         \
  }

__global__ void __launch_bounds__(NTHREADS, 1)
gru_persistent_kernel(const float* __restrict__ x,
                      const float* __restrict__ W_ih,
                      const float* __restrict__ W_hh,
                      const float* __restrict__ b_ih,
                      const float* __restrict__ b_hh,
                      const float* __restrict__ W_lin,
                      const float* __restrict__ b_lin,
                      float* __restrict__ out)
{
    extern __shared__ char smem_raw[];
    float4* ws4 = (float4*)smem_raw;                 // [48][WS_PITCH]
    float4* hs4 = ws4 + 48 * WS_PITCH;               // [64][HS_PITCH]
    float*  wih  = (float*)(hs4 + 64 * HS_PITCH);    // [48][WIH_PITCH]
    float*  xs   = wih + 48 * WIH_PITCH;             // [64][8]
    float*  bihs = xs + 64 * 8;                      // [48]
    float*  bhhs = bihs + 48;                        // [48]
    float*  wlin = bhhs + 48;                        // [16]

    const int tid = threadIdx.x;
    const int cta = blockIdx.x;
    const int bt  = cta / NCT;
    const int ct  = cta % NCT;
    const int b0  = bt * BT;
    const int j0  = ct * CT;

    // ---- one-time: weight slices into SMEM ----
    {
        const float4* whh4 = (const float4*)W_hh;
        for (int idx = tid; idx < 48 * 64; idx += NTHREADS) {
            int c = idx >> 6, k4 = idx & 63;
            int g = c >> 4, l = c & 15;
            int grow = g * HH + j0 + l;
            ws4[c * WS_PITCH + k4] = whh4[grow * (HH / 4) + k4];
        }
        for (int idx = tid; idx < 48 * WIH_PITCH; idx += NTHREADS) {
            int c = idx / WIH_PITCH, k = idx % WIH_PITCH;
            int g = c >> 4, l = c & 15;
            int grow = g * HH + j0 + l;
            wih[idx] = (k < II) ? W_ih[grow * II + k] : 0.0f;
        }
        if (tid < 48) {
            int g = tid >> 4, l = tid & 15;
            int grow = g * HH + j0 + l;
            bihs[tid] = b_ih[grow];
            bhhs[tid] = b_hh[grow];
        }
        if (tid < CT) wlin[tid] = W_lin[j0 + tid];
    }

    // ---- one-time: h0 = 0, out = b_lin (accumulated via atomics later) ----
    {
        float* h0 = &g_h[0][0][0];
        const int perH = (BB * HH) / NCTAS;          // 1024
        for (int i = tid; i < perH; i += NTHREADS) h0[cta * perH + i] = 0.0f;
        const float bl = b_lin[0];
        const int perO = (BB * TT) / NCTAS;          // 2048
        for (int i = tid; i < perO; i += NTHREADS) out[(size_t)cta * perO + i] = bl;
    }

    grid_barrier();

    const int ty = tid >> 4;                         // 0..15 -> 4 batch rows
    const int tx = tid & 15;                         // 0..15 -> 1 h-col (x3 gates)

    const ulonglong2* w0q = (const ulonglong2*)(ws4 + tx * WS_PITCH);
    const ulonglong2* w1q = (const ulonglong2*)(ws4 + (16 + tx) * WS_PITCH);
    const ulonglong2* w2q = (const ulonglong2*)(ws4 + (32 + tx) * WS_PITCH);
    const ulonglong2* hq[4];
    #pragma unroll
    for (int i = 0; i < 4; i++)
        hq[i] = (const ulonglong2*)(hs4 + (4 * ty + i) * HS_PITCH);

    const unsigned long long* wxr = (const unsigned long long*)&wih[tx * WIH_PITCH];
    const unsigned long long* wxz = (const unsigned long long*)&wih[(16 + tx) * WIH_PITCH];
    const unsigned long long* wxn = (const unsigned long long*)&wih[(32 + tx) * WIH_PITCH];

    for (int t = 0; t < TT; t++) {
        const int p = t & 1;

        // ---- async h-tile fetch: 4 chunks x 16KB via cp.async.cg (L2-only) ----
        const float4* hsrc = (const float4*)&g_h[p][b0][0];
        #pragma unroll
        for (int c = 0; c < 4; c++) {
            #pragma unroll
            for (int u = 0; u < 4; u++) {
                int idx = u * NTHREADS + tid;        // 0..1023
                int r = idx >> 4;
                int k4 = (idx & 15) + c * 16;
                unsigned dst = (unsigned)__cvta_generic_to_shared(
                                   &hs4[r * HS_PITCH + k4]);
                const float4* src = hsrc + r * 64 + k4;
                asm volatile("cp.async.cg.shared.global [%0], [%1], 16;"
                             :: "r"(dst), "l"(src) : "memory");
            }
            asm volatile("cp.async.commit_group;" ::: "memory");
        }

        // x_t tile [64][8] (read-only input, L1 fine)
        if (tid < BT * 2) {
            int r = tid >> 1, half = tid & 1;
            const float4* xsrc = (const float4*)&x[((size_t)(b0 + r) * TT + t) * II];
            ((float4*)xs)[r * 2 + half] = __ldg(&xsrc[half]);
        }

        // ---- GEMM: acc[g][i] = sum_k h[4ty+i][k] * W_hh[g*256+j0+tx][k] ----
        unsigned long long acc0[4], acc1[4], acc2[4];
        #pragma unroll
        for (int i = 0; i < 4; i++) { acc0[i] = 0ull; acc1[i] = 0ull; acc2[i] = 0ull; }

        CHUNK(0, 3)
        CHUNK(16, 2)
        CHUNK(32, 1)
        CHUNK(48, 0)

        // ---- fused gates + h update + pred partial ----
        float pred[4];
        #pragma unroll
        for (int i = 0; i < 4; i++) {
            const int r = 4 * ty + i;

            // x-part (packed pairs, K=8 -> 4 u64)
            const unsigned long long* xq =
                (const unsigned long long*)&xs[r * II];
            unsigned long long ar = 0ull, az = 0ull, an = 0ull;
            #pragma unroll
            for (int kq = 0; kq < 4; kq++) {
                unsigned long long xv = xq[kq];
                ffma2(ar, xv, wxr[kq]);
                ffma2(az, xv, wxz[kq]);
                ffma2(an, xv, wxn[kq]);
            }

            float rr = sigmoidf_fast(bihs[tx] + f2sum(ar) + f2sum(acc0[i]) + bhhs[tx]);
            float zz = sigmoidf_fast(bihs[16 + tx] + f2sum(az) + f2sum(acc1[i]) + bhhs[16 + tx]);
            float nn = tanh_fast(bihs[32 + tx] + f2sum(an) +
                                 rr * (f2sum(acc2[i]) + bhhs[32 + tx]));
            float hold = ((const float*)hs4)[r * (HS_PITCH * 4) + j0 + tx];
            float hn = (1.0f - zz) * nn + zz * hold;
            __stcg(&g_h[1 - p][b0 + r][j0 + tx], hn);
            pred[i] = hn * wlin[tx];
        }

        // reduce pred over 16 tx lanes, atomic into out
        #pragma unroll
        for (int i = 0; i < 4; i++) {
            float v = pred[i];
            v += __shfl_xor_sync(0xffffffffu, v, 1);
            v += __shfl_xor_sync(0xffffffffu, v, 2);
            v += __shfl_xor_sync(0xffffffffu, v, 4);
            v += __shfl_xor_sync(0xffffffffu, v, 8);
            if (tx == 0) atomicAdd(&out[(size_t)(b0 + 4 * ty + i) * TT + t], v);
        }

        grid_barrier();
    }
}

extern "C" void kernel_launch(void* const* d_in, const int* in_sizes, int n_in,
                              void* d_out, int out_size) {
    const float* x     = (const float*)d_in[0];
    const float* W_ih  = (const float*)d_in[1];
    const float* W_hh  = (const float*)d_in[2];
    const float* b_ih  = (const float*)d_in[3];
    const float* b_hh  = (const float*)d_in[4];
    const float* W_lin = (const float*)d_in[5];
    const float* b_lin = (const float*)d_in[6];
    float* out = (float*)d_out;

    size_t smem = (size_t)(48 * WS_PITCH + 64 * HS_PITCH) * sizeof(float4)
                + (size_t)(48 * WIH_PITCH + 64 * 8 + 48 + 48 + 16) * sizeof(float);

    cudaFuncSetAttribute(gru_persistent_kernel,
                         cudaFuncAttributeMaxDynamicSharedMemorySize, (int)smem);

    gru_persistent_kernel<<<NCTAS, NTHREADS, smem>>>(
        x, W_ih, W_hh, b_ih, b_hh, W_lin, b_lin, out);
}